// round 8
// baseline (speedup 1.0000x reference)
#include <cuda_runtime.h>
#include <cuda_bf16.h>
#include <math.h>

// Problem constants (fixed by the dataset)
#define NMAX 50000
#define EMAX 800000
#define F_IN 128
#define D1   256
#define D2   128
#define KCL  32
#define SCAN_NB 256   // max chunk blocks (ceil(50000/256)=196)

// ---------------- scratch (device globals; no allocation allowed) -------------
__device__ float g_xw [NMAX * D1];     // features @ W1          [N,256]
__device__ float g_H  [NMAX * D1];     // GCN output             [N,256]
__device__ float g_abs[NMAX * D2];     // tanh(H@fc1_W+b)        [N,128]
__device__ float g_S  [NMAX * KCL];    // softmax assignments    [N,32]
__device__ float g_LS [NMAX * KCL];    // L @ S                  [N,32]

__device__ int   g_cnt_in [NMAX];      // in-degree  (by col/target)
__device__ int   g_cnt_out[NMAX];      // out-degree (by row/source)
__device__ int   g_off_in [NMAX + 1];
__device__ int   g_off_out[NMAX + 1];
__device__ int   g_cur_in [NMAX];
__device__ int   g_cur_out[NMAX];
__device__ int   g_csr_in [EMAX];      // sources grouped by target
__device__ int   g_csr_out[EMAX];      // targets grouped by source
__device__ float g_dinv1[NMAX];        // GCN D^-1/2 (with self loop)
__device__ float g_dinv2[NMAX];        // Laplacian D^-1/2 (row degree)

__device__ int   g_blksum[2][SCAN_NB]; // per-chunk totals
__device__ int   g_blkoff[2][SCAN_NB]; // exclusive chunk offsets

__device__ float g_adj [KCL * KCL];    // S^T @ LS
__device__ float g_sumH[D1];           // column sums of H

// ---------------- small utility kernels ----------------
__global__ void zero_kernel(int n) {
    int i = blockIdx.x * blockDim.x + threadIdx.x;
    if (i < n) { g_cnt_in[i] = 0; g_cnt_out[i] = 0; }
    if (i < KCL * KCL) g_adj[i] = 0.f;
    if (i < D1) g_sumH[i] = 0.f;
}

// edges arrive as INT32 (JAX silently downcasts int64 without x64 mode).
__global__ void count_kernel(const int* __restrict__ edges, int E) {
    int e = blockIdx.x * blockDim.x + threadIdx.x;
    if (e >= E) return;
    int r = edges[e];        // source (row)
    int c = edges[E + e];    // target (col)
    atomicAdd(&g_cnt_in[c], 1);
    atomicAdd(&g_cnt_out[r], 1);
}

// ---------------- 3-phase scan (replaces the 82us 2-block scan) ----------------
// Phase 1: per-chunk totals.  grid = (nChunks, 2)
__global__ void scan_partial_kernel(int n) {
    const int* cnt = (blockIdx.y == 0) ? g_cnt_in : g_cnt_out;
    int idx = blockIdx.x * 256 + threadIdx.x;
    int v = (idx < n) ? cnt[idx] : 0;
    int lane = threadIdx.x & 31, wid = threadIdx.x >> 5;
    int x = v;
    #pragma unroll
    for (int o = 16; o > 0; o >>= 1) x += __shfl_xor_sync(0xffffffffu, x, o);
    __shared__ int ws[8];
    if (lane == 0) ws[wid] = x;
    __syncthreads();
    if (threadIdx.x == 0) {
        int t = 0;
        #pragma unroll
        for (int w = 0; w < 8; w++) t += ws[w];
        g_blksum[blockIdx.y][blockIdx.x] = t;
    }
}

// Phase 2: scan the chunk totals (<=256 of them). grid = 2 blocks of 256.
__global__ void scan_blocks_kernel(int nChunks, int n) {
    int which = blockIdx.x;
    __shared__ int sh[SCAN_NB];
    int t = threadIdx.x;
    sh[t] = (t < nChunks) ? g_blksum[which][t] : 0;
    __syncthreads();
    #pragma unroll
    for (int d = 1; d < SCAN_NB; d <<= 1) {
        int v = (t >= d) ? sh[t - d] : 0;
        __syncthreads();
        sh[t] += v;
        __syncthreads();
    }
    if (t < nChunks) g_blkoff[which][t] = sh[t] - g_blksum[which][t];  // exclusive
    if (t == 0) {
        int total = sh[SCAN_NB - 1];
        if (which == 0) g_off_in[n] = total; else g_off_out[n] = total;
    }
}

// Phase 3: in-block exclusive scan + chunk offset; also cursors and dinv.
__global__ void scan_final_kernel(int n) {
    int which = blockIdx.y;
    const int* cnt = (which == 0) ? g_cnt_in : g_cnt_out;
    int*       off = (which == 0) ? g_off_in : g_off_out;
    int*       cur = (which == 0) ? g_cur_in : g_cur_out;
    int idx = blockIdx.x * 256 + threadIdx.x;
    int v = (idx < n) ? cnt[idx] : 0;
    int lane = threadIdx.x & 31, wid = threadIdx.x >> 5;
    // warp inclusive scan
    int x = v;
    #pragma unroll
    for (int o = 1; o < 32; o <<= 1) {
        int t = __shfl_up_sync(0xffffffffu, x, o);
        if (lane >= o) x += t;
    }
    __shared__ int ws[8];
    if (lane == 31) ws[wid] = x;
    __syncthreads();
    if (wid == 0) {
        int wv = (lane < 8) ? ws[lane] : 0;
        #pragma unroll
        for (int o = 1; o < 8; o <<= 1) {
            int t = __shfl_up_sync(0xffffffffu, wv, o);
            if (lane >= o) wv += t;
        }
        if (lane < 8) ws[lane] = wv - ((lane < 8) ? ((lane==0)?wv: wv) : 0); // placeholder, fixed below
        // exclusive: store inclusive, subtract own below
        if (lane < 8) ws[lane] = wv;
    }
    __syncthreads();
    int warpExcl = (wid == 0) ? 0 : ws[wid - 1];
    int excl = g_blkoff[which][blockIdx.x] + warpExcl + (x - v);
    if (idx < n) {
        off[idx] = excl;
        cur[idx] = excl;
        if (which == 0) g_dinv1[idx] = rsqrtf((float)v + 1.0f);
        else            g_dinv2[idx] = (v > 0) ? rsqrtf((float)v) : 0.0f;
    }
}

__global__ void fill_kernel(const int* __restrict__ edges, int E) {
    int e = blockIdx.x * blockDim.x + threadIdx.x;
    if (e >= E) return;
    int r = edges[e];
    int c = edges[E + e];
    int p = atomicAdd(&g_cur_in[c], 1);
    g_csr_in[p] = r;
    int q = atomicAdd(&g_cur_out[r], 1);
    g_csr_out[q] = c;
}

// ---------------- tiled SGEMM v2: 128x128 tile, BK=16, 8x8 microtile ---------
// C = op(A@B + bias), row-major. EPI: 0 = none, 1 = tanh.
// Requires N % 128 == 0 (true: 256 and 128). M guarded.
template <int EPI>
__global__ __launch_bounds__(256, 2)
void gemm128_kernel(const float* __restrict__ A, const float* __restrict__ B,
                    const float* __restrict__ bias, float* __restrict__ C,
                    int M, int N, int K) {
    __shared__ float As[16][128];
    __shared__ float Bs[16][128];

    int tid = threadIdx.x;
    int tx = tid & 15;          // 0..15 -> col group (8 cols)
    int ty = tid >> 4;          // 0..15 -> row group (8 rows)
    int rowBase = blockIdx.y * 128;
    int colBase = blockIdx.x * 128;

    int aRow = tid >> 1;            // 0..127
    int aK   = (tid & 1) * 8;       // 0 or 8
    int bRow = tid >> 4;            // 0..15
    int bCol = (tid & 15) * 8;      // 0..120

    float acc[8][8] = {};
    for (int k0 = 0; k0 < K; k0 += 16) {
        int gr = rowBase + aRow;
        float4 a0, a1;
        if (gr < M) {
            const float* ap = &A[(long)gr * K + k0 + aK];
            a0 = *(const float4*)ap;
            a1 = *(const float4*)(ap + 4);
        } else {
            a0 = make_float4(0.f,0.f,0.f,0.f); a1 = a0;
        }
        As[aK+0][aRow]=a0.x; As[aK+1][aRow]=a0.y; As[aK+2][aRow]=a0.z; As[aK+3][aRow]=a0.w;
        As[aK+4][aRow]=a1.x; As[aK+5][aRow]=a1.y; As[aK+6][aRow]=a1.z; As[aK+7][aRow]=a1.w;
        {
            const float* bp = &B[(long)(k0 + bRow) * N + colBase + bCol];
            *(float4*)&Bs[bRow][bCol]     = *(const float4*)bp;
            *(float4*)&Bs[bRow][bCol + 4] = *(const float4*)(bp + 4);
        }
        __syncthreads();
        #pragma unroll
        for (int k = 0; k < 16; k++) {
            float a[8], b[8];
            *(float4*)&a[0] = *(const float4*)&As[k][ty * 8];
            *(float4*)&a[4] = *(const float4*)&As[k][ty * 8 + 4];
            *(float4*)&b[0] = *(const float4*)&Bs[k][tx * 8];
            *(float4*)&b[4] = *(const float4*)&Bs[k][tx * 8 + 4];
            #pragma unroll
            for (int i = 0; i < 8; i++)
                #pragma unroll
                for (int j = 0; j < 8; j++)
                    acc[i][j] += a[i] * b[j];
        }
        __syncthreads();
    }
    #pragma unroll
    for (int i = 0; i < 8; i++) {
        int r = rowBase + ty * 8 + i;
        if (r >= M) continue;
        #pragma unroll
        for (int j = 0; j < 8; j += 4) {
            int c = colBase + tx * 8 + j;
            float4 v;
            v.x = acc[i][j+0]; v.y = acc[i][j+1]; v.z = acc[i][j+2]; v.w = acc[i][j+3];
            if (bias) { v.x += bias[c]; v.y += bias[c+1]; v.z += bias[c+2]; v.w += bias[c+3]; }
            if (EPI == 1) { v.x = tanhf(v.x); v.y = tanhf(v.y); v.z = tanhf(v.z); v.w = tanhf(v.w); }
            *(float4*)&C[(long)r * N + c] = v;
        }
    }
}

// ---------------- GCN gather: H[i] = b1 + dinv1[i]^2*xw[i] + sum_j dinv1[j]dinv1[i]*xw[j]
__global__ void gcn_gather_kernel(const float* __restrict__ b1, int N) {
    int i = blockIdx.x;            // one node per block
    int t = threadIdx.x;           // 256 = D1
    float di = g_dinv1[i];
    float acc = di * di * g_xw[(long)i * D1 + t];
    int s = g_off_in[i], e = g_off_in[i + 1];
    for (int p = s; p < e; p++) {
        int j = g_csr_in[p];
        acc += di * g_dinv1[j] * g_xw[(long)j * D1 + t];
    }
    g_H[(long)i * D1 + t] = acc + b1[t];
}

// ---------------- fc2 + softmax: one warp per node, lane = cluster k ----------
__global__ void fc2_softmax_kernel(const float* __restrict__ fc2W,
                                   const float* __restrict__ fc2b, int N) {
    int warp = (blockIdx.x * blockDim.x + threadIdx.x) >> 5;
    int lane = threadIdx.x & 31;
    if (warp >= N) return;
    const float* a = g_abs + (long)warp * D2;
    float av[4];
    #pragma unroll
    for (int q = 0; q < 4; q++) av[q] = a[lane + 32 * q];
    float acc = fc2b[lane];
    #pragma unroll
    for (int q = 0; q < 4; q++) {
        #pragma unroll
        for (int kk = 0; kk < 32; kk++) {
            float aval = __shfl_sync(0xffffffffu, av[q], kk);
            acc += aval * fc2W[(q * 32 + kk) * KCL + lane];
        }
    }
    float m = acc;
    #pragma unroll
    for (int o = 16; o > 0; o >>= 1) m = fmaxf(m, __shfl_xor_sync(0xffffffffu, m, o));
    float ex = __expf(acc - m);
    float sum = ex;
    #pragma unroll
    for (int o = 16; o > 0; o >>= 1) sum += __shfl_xor_sync(0xffffffffu, sum, o);
    g_S[(long)warp * KCL + lane] = ex / sum;
}

// ---------------- LS = S + gather of -(dinv2[r]dinv2[c]) * S[c] over r's out-edges
__global__ void ls_kernel(int N) {
    int warp = (blockIdx.x * blockDim.x + threadIdx.x) >> 5;
    int lane = threadIdx.x & 31;
    if (warp >= N) return;
    float di = g_dinv2[warp];
    float acc = g_S[(long)warp * KCL + lane];
    int s = g_off_out[warp], e = g_off_out[warp + 1];
    for (int p = s; p < e; p++) {
        int c = g_csr_out[p];
        acc -= di * g_dinv2[c] * g_S[(long)c * KCL + lane];
    }
    g_LS[(long)warp * KCL + lane] = acc;
}

// ---------------- new_adj = S^T @ LS (32x32), partial per block + atomics -----
__global__ void adj_kernel(int N) {
    int tid = threadIdx.x;         // 1024
    int i = tid >> 5, j = tid & 31;
    float acc = 0.f;
    for (int n = blockIdx.x; n < N; n += gridDim.x)
        acc += g_S[(long)n * KCL + i] * g_LS[(long)n * KCL + j];
    atomicAdd(&g_adj[i * KCL + j], acc);
}

// ---------------- column sums of H ----------------
__global__ void sumH_kernel(int N) {
    int t = threadIdx.x;           // 256
    float acc = 0.f;
    for (int n = blockIdx.x; n < N; n += gridDim.x)
        acc += g_H[(long)n * D1 + t];
    atomicAdd(&g_sumH[t], acc);
}

// ---------------- finalize: embedding + pos_penalty ----------------
__global__ void finalize_kernel(float* __restrict__ out, int out_size) {
    int t = threadIdx.x;           // 256
    if (t < D1 && t < out_size) out[t] = g_sumH[t] * (1.0f / KCL);
    if (t < 32) {
        float rowsum = 0.f;
        #pragma unroll
        for (int c = 0; c < KCL; c++) rowsum += fabsf(g_adj[t * KCL + c]);
        float d = g_adj[t * KCL + t] / fmaxf(rowsum, 1e-12f);
        // MSE(norm_diag broadcast vs eye): column t contributes (K-1)*d^2 + (d-1)^2
        float val = (KCL - 1) * d * d + (d - 1.f) * (d - 1.f);
        #pragma unroll
        for (int o = 16; o > 0; o >>= 1) val += __shfl_xor_sync(0xffffffffu, val, o);
        if (t == 0 && D1 < out_size) out[D1] = val * (1.0f / (KCL * KCL));
    }
}

// ---------------- launch ----------------
extern "C" void kernel_launch(void* const* d_in, const int* in_sizes, int n_in,
                              void* d_out, int out_size) {
    const float* features = (const float*)d_in[0];      // [N,128] f32
    const int*   edges    = (const int*)d_in[1];        // [2,E]  int32 (JAX downcasts int64)
    const float* W1       = (const float*)d_in[2];      // [128,256]
    const float* b1       = (const float*)d_in[3];      // [256]
    const float* fc1W     = (const float*)d_in[4];      // [256,128]
    const float* fc1b     = (const float*)d_in[5];      // [128]
    const float* fc2W     = (const float*)d_in[6];      // [128,32]
    const float* fc2b     = (const float*)d_in[7];      // [32]
    float* out = (float*)d_out;

    int N = in_sizes[0] / F_IN;
    int E = in_sizes[1] / 2;
    int nChunks = (N + 255) / 256;

    float *p_xw = nullptr, *p_H = nullptr, *p_abs = nullptr;
    cudaGetSymbolAddress((void**)&p_xw,  g_xw);
    cudaGetSymbolAddress((void**)&p_H,   g_H);
    cudaGetSymbolAddress((void**)&p_abs, g_abs);

    // 1. CSR build
    zero_kernel<<<(N + 255) / 256, 256>>>(N);
    count_kernel<<<(E + 255) / 256, 256>>>(edges, E);
    {
        dim3 g1(nChunks, 2);
        scan_partial_kernel<<<g1, 256>>>(N);
        scan_blocks_kernel<<<2, SCAN_NB>>>(nChunks, N);
        scan_final_kernel<<<g1, 256>>>(N);   // also writes cursors + dinv
    }
    fill_kernel<<<(E + 255) / 256, 256>>>(edges, E);

    // 2. xw = features @ W1   [N,256]
    {
        dim3 grid(D1 / 128, (N + 127) / 128);
        gemm128_kernel<0><<<grid, 256>>>(features, W1, nullptr, p_xw, N, D1, F_IN);
    }

    // 3. GCN aggregation -> H
    gcn_gather_kernel<<<N, D1>>>(b1, N);

    // 4. abstract = tanh(H @ fc1W + fc1b)  [N,128]
    {
        dim3 grid(D2 / 128, (N + 127) / 128);
        gemm128_kernel<1><<<grid, 256>>>(p_H, fc1W, fc1b, p_abs, N, D2, D1);
    }

    // 5. S = softmax(abstract @ fc2W + fc2b)  [N,32]
    fc2_softmax_kernel<<<(N * 32 + 255) / 256, 256>>>(fc2W, fc2b, N);

    // 6. LS = L @ S
    ls_kernel<<<(N * 32 + 255) / 256, 256>>>(N);

    // 7. new_adj = S^T @ LS ; sumH
    adj_kernel<<<148, 1024>>>(N);
    sumH_kernel<<<256, 256>>>(N);

    // 8. outputs
    finalize_kernel<<<1, 256>>>(out, out_size);
}

// round 11
// speedup vs baseline: 1.3811x; 1.3811x over previous
#include <cuda_runtime.h>
#include <cuda_bf16.h>
#include <math.h>

// Problem constants (fixed by the dataset)
#define NMAX 50000
#define EMAX 800000
#define F_IN 128
#define D1   256
#define D2   128
#define KCL  32
#define SCAN_NB 256   // max chunk blocks (ceil(50000/256)=196)

// ---------------- scratch (device globals; no allocation allowed) -------------
__device__ float g_xw [NMAX * D1];     // features @ W1          [N,256]
__device__ float g_H  [NMAX * D1];     // GCN output             [N,256]
__device__ float g_abs[NMAX * D2];     // tanh(H@fc1_W+b)        [N,128]
__device__ float g_S  [NMAX * KCL];    // softmax assignments    [N,32]
__device__ float g_LS [NMAX * KCL];    // L @ S                  [N,32]

__device__ int   g_cnt_in [NMAX];      // in-degree  (by col/target)
__device__ int   g_cnt_out[NMAX];      // out-degree (by row/source)
__device__ int   g_off_in [NMAX + 1];
__device__ int   g_off_out[NMAX + 1];
__device__ int   g_cur_in [NMAX];
__device__ int   g_cur_out[NMAX];
__device__ int   g_csr_in [EMAX];      // sources grouped by target
__device__ int   g_csr_out[EMAX];      // targets grouped by source
__device__ float g_dinv1[NMAX];        // GCN D^-1/2 (with self loop)
__device__ float g_dinv2[NMAX];        // Laplacian D^-1/2 (row degree)

__device__ int   g_blksum[2][SCAN_NB]; // per-chunk totals
__device__ int   g_blkoff[2][SCAN_NB]; // exclusive chunk offsets

__device__ float g_adj [KCL * KCL];    // S^T @ LS
__device__ float g_sumH[D1];           // column sums of H

// ---------------- small utility kernels ----------------
__global__ void zero_kernel(int n) {
    int i = blockIdx.x * blockDim.x + threadIdx.x;
    if (i < n) { g_cnt_in[i] = 0; g_cnt_out[i] = 0; }
    if (i < KCL * KCL) g_adj[i] = 0.f;
    if (i < D1) g_sumH[i] = 0.f;
}

// edges arrive as INT32 (JAX silently downcasts int64 without x64 mode).
__global__ void count_kernel(const int* __restrict__ edges, int E) {
    int e = blockIdx.x * blockDim.x + threadIdx.x;
    if (e >= E) return;
    int r = edges[e];        // source (row)
    int c = edges[E + e];    // target (col)
    atomicAdd(&g_cnt_in[c], 1);
    atomicAdd(&g_cnt_out[r], 1);
}

// ---------------- 3-phase scan ----------------
// Phase 1: per-chunk totals.  grid = (nChunks, 2)
__global__ void scan_partial_kernel(int n) {
    const int* cnt = (blockIdx.y == 0) ? g_cnt_in : g_cnt_out;
    int idx = blockIdx.x * 256 + threadIdx.x;
    int v = (idx < n) ? cnt[idx] : 0;
    int lane = threadIdx.x & 31, wid = threadIdx.x >> 5;
    int x = v;
    #pragma unroll
    for (int o = 16; o > 0; o >>= 1) x += __shfl_xor_sync(0xffffffffu, x, o);
    __shared__ int ws[8];
    if (lane == 0) ws[wid] = x;
    __syncthreads();
    if (threadIdx.x == 0) {
        int t = 0;
        #pragma unroll
        for (int w = 0; w < 8; w++) t += ws[w];
        g_blksum[blockIdx.y][blockIdx.x] = t;
    }
}

// Phase 2: scan the chunk totals (<=256 of them). grid = 2 blocks of 256.
__global__ void scan_blocks_kernel(int nChunks, int n) {
    int which = blockIdx.x;
    __shared__ int sh[SCAN_NB];
    int t = threadIdx.x;
    sh[t] = (t < nChunks) ? g_blksum[which][t] : 0;
    __syncthreads();
    #pragma unroll
    for (int d = 1; d < SCAN_NB; d <<= 1) {
        int v = (t >= d) ? sh[t - d] : 0;
        __syncthreads();
        sh[t] += v;
        __syncthreads();
    }
    if (t < nChunks) g_blkoff[which][t] = sh[t] - g_blksum[which][t];  // exclusive
    if (t == 0) {
        int total = sh[SCAN_NB - 1];
        if (which == 0) g_off_in[n] = total; else g_off_out[n] = total;
    }
}

// Phase 3: in-block exclusive scan + chunk offset; also cursors and dinv.
__global__ void scan_final_kernel(int n) {
    int which = blockIdx.y;
    const int* cnt = (which == 0) ? g_cnt_in : g_cnt_out;
    int*       off = (which == 0) ? g_off_in : g_off_out;
    int*       cur = (which == 0) ? g_cur_in : g_cur_out;
    int idx = blockIdx.x * 256 + threadIdx.x;
    int v = (idx < n) ? cnt[idx] : 0;
    int lane = threadIdx.x & 31, wid = threadIdx.x >> 5;
    // warp inclusive scan
    int x = v;
    #pragma unroll
    for (int o = 1; o < 32; o <<= 1) {
        int t = __shfl_up_sync(0xffffffffu, x, o);
        if (lane >= o) x += t;
    }
    __shared__ int ws[8];
    if (lane == 31) ws[wid] = x;
    __syncthreads();
    if (wid == 0) {
        int wv = (lane < 8) ? ws[lane] : 0;
        #pragma unroll
        for (int o = 1; o < 8; o <<= 1) {
            int t = __shfl_up_sync(0xffffffffu, wv, o);
            if (lane >= o) wv += t;
        }
        if (lane < 8) ws[lane] = wv;   // inclusive warp-total scan
    }
    __syncthreads();
    int warpExcl = (wid == 0) ? 0 : ws[wid - 1];
    int excl = g_blkoff[which][blockIdx.x] + warpExcl + (x - v);
    if (idx < n) {
        off[idx] = excl;
        cur[idx] = excl;
        if (which == 0) g_dinv1[idx] = rsqrtf((float)v + 1.0f);
        else            g_dinv2[idx] = (v > 0) ? rsqrtf((float)v) : 0.0f;
    }
}

__global__ void fill_kernel(const int* __restrict__ edges, int E) {
    int e = blockIdx.x * blockDim.x + threadIdx.x;
    if (e >= E) return;
    int r = edges[e];
    int c = edges[E + e];
    int p = atomicAdd(&g_cur_in[c], 1);
    g_csr_in[p] = r;
    int q = atomicAdd(&g_cur_out[r], 1);
    g_csr_out[q] = c;
}

// ---------------- tiled SGEMM (R7 proven): 64x64 tile, BK=16, 4x4 microtile --
// C = op(A@B + bias), row-major. EPI: 0 = none, 1 = tanh
template <int EPI>
__global__ void gemm_kernel(const float* __restrict__ A, const float* __restrict__ B,
                            const float* __restrict__ bias, float* __restrict__ C,
                            int M, int N, int K) {
    const int BM = 64, BN = 64, BK = 16;
    __shared__ float As[BK][BM];
    __shared__ float Bs[BK][BN];

    int tid = threadIdx.x;                 // 256
    int tx = tid & 15, ty = tid >> 4;      // 16x16 thread grid, 4x4 microtile
    int rowBase = blockIdx.y * BM;
    int colBase = blockIdx.x * BN;

    int aRow  = tid >> 2;                  // 0..63
    int aCol4 = (tid & 3) * 4;             // 0,4,8,12
    int bRow  = tid >> 4;                  // 0..15
    int bCol4 = (tid & 15) * 4;

    float acc[4][4] = {};
    for (int k0 = 0; k0 < K; k0 += BK) {
        int gr = rowBase + aRow;
        #pragma unroll
        for (int i = 0; i < 4; i++) {
            int gc = k0 + aCol4 + i;
            As[aCol4 + i][aRow] = (gr < M) ? A[(long)gr * K + gc] : 0.f;
        }
        {
            const float4 bv = *(const float4*)&B[(long)(k0 + bRow) * N + colBase + bCol4];
            *(float4*)&Bs[bRow][bCol4] = bv;
        }
        __syncthreads();
        #pragma unroll
        for (int k = 0; k < BK; k++) {
            float4 a4 = *(const float4*)&As[k][ty * 4];
            float4 b4 = *(const float4*)&Bs[k][tx * 4];
            float a[4] = {a4.x, a4.y, a4.z, a4.w};
            float b[4] = {b4.x, b4.y, b4.z, b4.w};
            #pragma unroll
            for (int i = 0; i < 4; i++)
                #pragma unroll
                for (int j = 0; j < 4; j++)
                    acc[i][j] += a[i] * b[j];
        }
        __syncthreads();
    }
    #pragma unroll
    for (int i = 0; i < 4; i++) {
        int r = rowBase + ty * 4 + i;
        if (r >= M) continue;
        #pragma unroll
        for (int j = 0; j < 4; j++) {
            int c = colBase + tx * 4 + j;
            float v = acc[i][j];
            if (bias) v += bias[c];
            if (EPI == 1) v = tanhf(v);
            C[(long)r * N + c] = v;
        }
    }
}

// ---------------- GCN gather: H[i] = b1 + dinv1[i]^2*xw[i] + sum_j dinv1[j]dinv1[i]*xw[j]
__global__ void gcn_gather_kernel(const float* __restrict__ b1, int N) {
    int i = blockIdx.x;            // one node per block
    int t = threadIdx.x;           // 256 = D1
    float di = g_dinv1[i];
    float acc = di * di * g_xw[(long)i * D1 + t];
    int s = g_off_in[i], e = g_off_in[i + 1];
    for (int p = s; p < e; p++) {
        int j = g_csr_in[p];
        acc += di * g_dinv1[j] * g_xw[(long)j * D1 + t];
    }
    g_H[(long)i * D1 + t] = acc + b1[t];
}

// ---------------- fc2 + softmax: one warp per node, lane = cluster k ----------
__global__ void fc2_softmax_kernel(const float* __restrict__ fc2W,
                                   const float* __restrict__ fc2b, int N) {
    int warp = (blockIdx.x * blockDim.x + threadIdx.x) >> 5;
    int lane = threadIdx.x & 31;
    if (warp >= N) return;
    const float* a = g_abs + (long)warp * D2;
    float av[4];
    #pragma unroll
    for (int q = 0; q < 4; q++) av[q] = a[lane + 32 * q];
    float acc = fc2b[lane];
    #pragma unroll
    for (int q = 0; q < 4; q++) {
        #pragma unroll
        for (int kk = 0; kk < 32; kk++) {
            float aval = __shfl_sync(0xffffffffu, av[q], kk);
            acc += aval * fc2W[(q * 32 + kk) * KCL + lane];
        }
    }
    float m = acc;
    #pragma unroll
    for (int o = 16; o > 0; o >>= 1) m = fmaxf(m, __shfl_xor_sync(0xffffffffu, m, o));
    float ex = __expf(acc - m);
    float sum = ex;
    #pragma unroll
    for (int o = 16; o > 0; o >>= 1) sum += __shfl_xor_sync(0xffffffffu, sum, o);
    g_S[(long)warp * KCL + lane] = ex / sum;
}

// ---------------- LS = S + gather of -(dinv2[r]dinv2[c]) * S[c] over r's out-edges
__global__ void ls_kernel(int N) {
    int warp = (blockIdx.x * blockDim.x + threadIdx.x) >> 5;
    int lane = threadIdx.x & 31;
    if (warp >= N) return;
    float di = g_dinv2[warp];
    float acc = g_S[(long)warp * KCL + lane];
    int s = g_off_out[warp], e = g_off_out[warp + 1];
    for (int p = s; p < e; p++) {
        int c = g_csr_out[p];
        acc -= di * g_dinv2[c] * g_S[(long)c * KCL + lane];
    }
    g_LS[(long)warp * KCL + lane] = acc;
}

// ---------------- new_adj = S^T @ LS (32x32), partial per block + atomics -----
__global__ void adj_kernel(int N) {
    int tid = threadIdx.x;         // 1024
    int i = tid >> 5, j = tid & 31;
    float acc = 0.f;
    for (int n = blockIdx.x; n < N; n += gridDim.x)
        acc += g_S[(long)n * KCL + i] * g_LS[(long)n * KCL + j];
    atomicAdd(&g_adj[i * KCL + j], acc);
}

// ---------------- column sums of H ----------------
__global__ void sumH_kernel(int N) {
    int t = threadIdx.x;           // 256
    float acc = 0.f;
    for (int n = blockIdx.x; n < N; n += gridDim.x)
        acc += g_H[(long)n * D1 + t];
    atomicAdd(&g_sumH[t], acc);
}

// ---------------- finalize: embedding + pos_penalty ----------------
__global__ void finalize_kernel(float* __restrict__ out, int out_size) {
    int t = threadIdx.x;           // 256
    if (t < D1 && t < out_size) out[t] = g_sumH[t] * (1.0f / KCL);
    if (t < 32) {
        float rowsum = 0.f;
        #pragma unroll
        for (int c = 0; c < KCL; c++) rowsum += fabsf(g_adj[t * KCL + c]);
        float d = g_adj[t * KCL + t] / fmaxf(rowsum, 1e-12f);
        // MSE(norm_diag broadcast vs eye): column t contributes (K-1)*d^2 + (d-1)^2
        float val = (KCL - 1) * d * d + (d - 1.f) * (d - 1.f);
        #pragma unroll
        for (int o = 16; o > 0; o >>= 1) val += __shfl_xor_sync(0xffffffffu, val, o);
        if (t == 0 && D1 < out_size) out[D1] = val * (1.0f / (KCL * KCL));
    }
}

// ---------------- launch ----------------
extern "C" void kernel_launch(void* const* d_in, const int* in_sizes, int n_in,
                              void* d_out, int out_size) {
    const float* features = (const float*)d_in[0];      // [N,128] f32
    const int*   edges    = (const int*)d_in[1];        // [2,E]  int32 (JAX downcasts int64)
    const float* W1       = (const float*)d_in[2];      // [128,256]
    const float* b1       = (const float*)d_in[3];      // [256]
    const float* fc1W     = (const float*)d_in[4];      // [256,128]
    const float* fc1b     = (const float*)d_in[5];      // [128]
    const float* fc2W     = (const float*)d_in[6];      // [128,32]
    const float* fc2b     = (const float*)d_in[7];      // [32]
    float* out = (float*)d_out;

    int N = in_sizes[0] / F_IN;
    int E = in_sizes[1] / 2;
    int nChunks = (N + 255) / 256;

    float *p_xw = nullptr, *p_H = nullptr, *p_abs = nullptr;
    cudaGetSymbolAddress((void**)&p_xw,  g_xw);
    cudaGetSymbolAddress((void**)&p_H,   g_H);
    cudaGetSymbolAddress((void**)&p_abs, g_abs);

    // 1. CSR build (3-phase scan: measured ~12us total vs 82us in R7)
    zero_kernel<<<(N + 255) / 256, 256>>>(N);
    count_kernel<<<(E + 255) / 256, 256>>>(edges, E);
    {
        dim3 g1(nChunks, 2);
        scan_partial_kernel<<<g1, 256>>>(N);
        scan_blocks_kernel<<<2, SCAN_NB>>>(nChunks, N);
        scan_final_kernel<<<g1, 256>>>(N);   // also writes cursors + dinv
    }
    fill_kernel<<<(E + 255) / 256, 256>>>(edges, E);

    // 2. xw = features @ W1   [N,256]   (R7-proven 64x64 GEMM)
    {
        dim3 grid(D1 / 64, (N + 63) / 64);
        gemm_kernel<0><<<grid, 256>>>(features, W1, nullptr, p_xw, N, D1, F_IN);
    }

    // 3. GCN aggregation -> H
    gcn_gather_kernel<<<N, D1>>>(b1, N);

    // 4. abstract = tanh(H @ fc1W + fc1b)  [N,128]
    {
        dim3 grid(D2 / 64, (N + 63) / 64);
        gemm_kernel<1><<<grid, 256>>>(p_H, fc1W, fc1b, p_abs, N, D2, D1);
    }

    // 5. S = softmax(abstract @ fc2W + fc2b)  [N,32]
    fc2_softmax_kernel<<<(N * 32 + 255) / 256, 256>>>(fc2W, fc2b, N);

    // 6. LS = L @ S
    ls_kernel<<<(N * 32 + 255) / 256, 256>>>(N);

    // 7. new_adj = S^T @ LS ; sumH
    adj_kernel<<<148, 1024>>>(N);
    sumH_kernel<<<256, 256>>>(N);

    // 8. outputs
    finalize_kernel<<<1, 256>>>(out, out_size);
}

// round 13
// speedup vs baseline: 1.6566x; 1.1995x over previous
#include <cuda_runtime.h>
#include <cuda_bf16.h>
#include <math.h>

// Problem constants (fixed by the dataset)
#define NMAX 50000
#define EMAX 800000
#define F_IN 128
#define D1   256
#define D2   128
#define KCL  32
#define SCAN_NB 256   // max chunk blocks (ceil(50000/256)=196)

// ---------------- scratch (device globals; no allocation allowed) -------------
__device__ float g_H  [NMAX * D1];     // GCN output             [N,256]
__device__ float g_abs[NMAX * D2];     // DUAL USE: agg=A_hat@X [N,128], then tanh(H@fc1_W+b)
__device__ float g_S  [NMAX * KCL];    // softmax assignments    [N,32]
__device__ float g_LS [NMAX * KCL];    // L @ S                  [N,32]

__device__ int   g_cnt_in [NMAX];      // in-degree  (by col/target)
__device__ int   g_cnt_out[NMAX];      // out-degree (by row/source)
__device__ int   g_off_in [NMAX + 1];
__device__ int   g_off_out[NMAX + 1];
__device__ int   g_cur_in [NMAX];
__device__ int   g_cur_out[NMAX];
__device__ int   g_csr_in [EMAX];      // sources grouped by target
__device__ int   g_csr_out[EMAX];      // targets grouped by source
__device__ float g_dinv1[NMAX];        // GCN D^-1/2 (with self loop)
__device__ float g_dinv2[NMAX];        // Laplacian D^-1/2 (row degree)

__device__ int   g_blksum[2][SCAN_NB]; // per-chunk totals
__device__ int   g_blkoff[2][SCAN_NB]; // exclusive chunk offsets

__device__ float g_adj [KCL * KCL];    // S^T @ LS
__device__ float g_sumH[D1];           // column sums of H

// ---------------- small utility kernels ----------------
__global__ void zero_kernel(int n) {
    int i = blockIdx.x * blockDim.x + threadIdx.x;
    if (i < n) { g_cnt_in[i] = 0; g_cnt_out[i] = 0; }
    if (i < KCL * KCL) g_adj[i] = 0.f;
    if (i < D1) g_sumH[i] = 0.f;
}

// edges arrive as INT32 (JAX silently downcasts int64 without x64 mode).
__global__ void count_kernel(const int* __restrict__ edges, int E) {
    int e = blockIdx.x * blockDim.x + threadIdx.x;
    if (e >= E) return;
    int r = edges[e];        // source (row)
    int c = edges[E + e];    // target (col)
    atomicAdd(&g_cnt_in[c], 1);
    atomicAdd(&g_cnt_out[r], 1);
}

// ---------------- 3-phase scan ----------------
// Phase 1: per-chunk totals.  grid = (nChunks, 2)
__global__ void scan_partial_kernel(int n) {
    const int* cnt = (blockIdx.y == 0) ? g_cnt_in : g_cnt_out;
    int idx = blockIdx.x * 256 + threadIdx.x;
    int v = (idx < n) ? cnt[idx] : 0;
    int lane = threadIdx.x & 31, wid = threadIdx.x >> 5;
    int x = v;
    #pragma unroll
    for (int o = 16; o > 0; o >>= 1) x += __shfl_xor_sync(0xffffffffu, x, o);
    __shared__ int ws[8];
    if (lane == 0) ws[wid] = x;
    __syncthreads();
    if (threadIdx.x == 0) {
        int t = 0;
        #pragma unroll
        for (int w = 0; w < 8; w++) t += ws[w];
        g_blksum[blockIdx.y][blockIdx.x] = t;
    }
}

// Phase 2: scan the chunk totals (<=256 of them). grid = 2 blocks of 256.
__global__ void scan_blocks_kernel(int nChunks, int n) {
    int which = blockIdx.x;
    __shared__ int sh[SCAN_NB];
    int t = threadIdx.x;
    sh[t] = (t < nChunks) ? g_blksum[which][t] : 0;
    __syncthreads();
    #pragma unroll
    for (int d = 1; d < SCAN_NB; d <<= 1) {
        int v = (t >= d) ? sh[t - d] : 0;
        __syncthreads();
        sh[t] += v;
        __syncthreads();
    }
    if (t < nChunks) g_blkoff[which][t] = sh[t] - g_blksum[which][t];  // exclusive
    if (t == 0) {
        int total = sh[SCAN_NB - 1];
        if (which == 0) g_off_in[n] = total; else g_off_out[n] = total;
    }
}

// Phase 3: in-block exclusive scan + chunk offset; also cursors and dinv.
__global__ void scan_final_kernel(int n) {
    int which = blockIdx.y;
    const int* cnt = (which == 0) ? g_cnt_in : g_cnt_out;
    int*       off = (which == 0) ? g_off_in : g_off_out;
    int*       cur = (which == 0) ? g_cur_in : g_cur_out;
    int idx = blockIdx.x * 256 + threadIdx.x;
    int v = (idx < n) ? cnt[idx] : 0;
    int lane = threadIdx.x & 31, wid = threadIdx.x >> 5;
    int x = v;
    #pragma unroll
    for (int o = 1; o < 32; o <<= 1) {
        int t = __shfl_up_sync(0xffffffffu, x, o);
        if (lane >= o) x += t;
    }
    __shared__ int ws[8];
    if (lane == 31) ws[wid] = x;
    __syncthreads();
    if (wid == 0) {
        int wv = (lane < 8) ? ws[lane] : 0;
        #pragma unroll
        for (int o = 1; o < 8; o <<= 1) {
            int t = __shfl_up_sync(0xffffffffu, wv, o);
            if (lane >= o) wv += t;
        }
        if (lane < 8) ws[lane] = wv;   // inclusive warp-total scan
    }
    __syncthreads();
    int warpExcl = (wid == 0) ? 0 : ws[wid - 1];
    int excl = g_blkoff[which][blockIdx.x] + warpExcl + (x - v);
    if (idx < n) {
        off[idx] = excl;
        cur[idx] = excl;
        if (which == 0) g_dinv1[idx] = rsqrtf((float)v + 1.0f);
        else            g_dinv2[idx] = (v > 0) ? rsqrtf((float)v) : 0.0f;
    }
}

__global__ void fill_kernel(const int* __restrict__ edges, int E) {
    int e = blockIdx.x * blockDim.x + threadIdx.x;
    if (e >= E) return;
    int r = edges[e];
    int c = edges[E + e];
    int p = atomicAdd(&g_cur_in[c], 1);
    g_csr_in[p] = r;
    int q = atomicAdd(&g_cur_out[r], 1);
    g_csr_out[q] = c;
}

// ---------------- feature aggregation: agg[i] = dinv1[i]^2*X[i] + sum_j dinv1[i]dinv1[j]*X[j]
// (GCN identity: A_hat (X W) = (A_hat X) W — aggregate 128-wide features BEFORE the GEMM,
//  halving gather traffic vs aggregating the 256-wide xw.)
// One warp per node; lane holds a float4 (32 lanes x 4 = 128 floats).
__global__ void agg_gather_kernel(const float* __restrict__ feat,
                                  float* __restrict__ agg, int N) {
    int w = (blockIdx.x * blockDim.x + threadIdx.x) >> 5;
    int lane = threadIdx.x & 31;
    if (w >= N) return;
    const float4* f4 = (const float4*)feat;
    float di = g_dinv1[w];
    float4 v = f4[(long)w * 32 + lane];
    float s0 = di * di;
    float4 acc;
    acc.x = s0 * v.x; acc.y = s0 * v.y; acc.z = s0 * v.z; acc.w = s0 * v.w;
    int s = g_off_in[w], e = g_off_in[w + 1];
    for (int p = s; p < e; p++) {
        int j = g_csr_in[p];
        float sc = di * g_dinv1[j];
        float4 x = f4[(long)j * 32 + lane];
        acc.x += sc * x.x; acc.y += sc * x.y; acc.z += sc * x.z; acc.w += sc * x.w;
    }
    ((float4*)agg)[(long)w * 32 + lane] = acc;
}

// ---------------- tiled SGEMM (R7 proven): 64x64 tile, BK=16, 4x4 microtile --
// C = op(A@B + bias), row-major. EPI: 0 = none, 1 = tanh
template <int EPI>
__global__ void gemm_kernel(const float* __restrict__ A, const float* __restrict__ B,
                            const float* __restrict__ bias, float* __restrict__ C,
                            int M, int N, int K) {
    const int BM = 64, BN = 64, BK = 16;
    __shared__ float As[BK][BM];
    __shared__ float Bs[BK][BN];

    int tid = threadIdx.x;                 // 256
    int tx = tid & 15, ty = tid >> 4;      // 16x16 thread grid, 4x4 microtile
    int rowBase = blockIdx.y * BM;
    int colBase = blockIdx.x * BN;

    int aRow  = tid >> 2;                  // 0..63
    int aCol4 = (tid & 3) * 4;             // 0,4,8,12
    int bRow  = tid >> 4;                  // 0..15
    int bCol4 = (tid & 15) * 4;

    float acc[4][4] = {};
    for (int k0 = 0; k0 < K; k0 += BK) {
        int gr = rowBase + aRow;
        #pragma unroll
        for (int i = 0; i < 4; i++) {
            int gc = k0 + aCol4 + i;
            As[aCol4 + i][aRow] = (gr < M) ? A[(long)gr * K + gc] : 0.f;
        }
        {
            const float4 bv = *(const float4*)&B[(long)(k0 + bRow) * N + colBase + bCol4];
            *(float4*)&Bs[bRow][bCol4] = bv;
        }
        __syncthreads();
        #pragma unroll
        for (int k = 0; k < BK; k++) {
            float4 a4 = *(const float4*)&As[k][ty * 4];
            float4 b4 = *(const float4*)&Bs[k][tx * 4];
            float a[4] = {a4.x, a4.y, a4.z, a4.w};
            float b[4] = {b4.x, b4.y, b4.z, b4.w};
            #pragma unroll
            for (int i = 0; i < 4; i++)
                #pragma unroll
                for (int j = 0; j < 4; j++)
                    acc[i][j] += a[i] * b[j];
        }
        __syncthreads();
    }
    #pragma unroll
    for (int i = 0; i < 4; i++) {
        int r = rowBase + ty * 4 + i;
        if (r >= M) continue;
        #pragma unroll
        for (int j = 0; j < 4; j++) {
            int c = colBase + tx * 4 + j;
            float v = acc[i][j];
            if (bias) v += bias[c];
            if (EPI == 1) v = tanhf(v);
            C[(long)r * N + c] = v;
        }
    }
}

// ---------------- fc2 + softmax: one warp per node, lane = cluster k ----------
__global__ void fc2_softmax_kernel(const float* __restrict__ fc2W,
                                   const float* __restrict__ fc2b, int N) {
    int warp = (blockIdx.x * blockDim.x + threadIdx.x) >> 5;
    int lane = threadIdx.x & 31;
    if (warp >= N) return;
    const float* a = g_abs + (long)warp * D2;
    float av[4];
    #pragma unroll
    for (int q = 0; q < 4; q++) av[q] = a[lane + 32 * q];
    float acc = fc2b[lane];
    #pragma unroll
    for (int q = 0; q < 4; q++) {
        #pragma unroll
        for (int kk = 0; kk < 32; kk++) {
            float aval = __shfl_sync(0xffffffffu, av[q], kk);
            acc += aval * fc2W[(q * 32 + kk) * KCL + lane];
        }
    }
    float m = acc;
    #pragma unroll
    for (int o = 16; o > 0; o >>= 1) m = fmaxf(m, __shfl_xor_sync(0xffffffffu, m, o));
    float ex = __expf(acc - m);
    float sum = ex;
    #pragma unroll
    for (int o = 16; o > 0; o >>= 1) sum += __shfl_xor_sync(0xffffffffu, sum, o);
    g_S[(long)warp * KCL + lane] = ex / sum;
}

// ---------------- LS = S + gather of -(dinv2[r]dinv2[c]) * S[c] over r's out-edges
__global__ void ls_kernel(int N) {
    int warp = (blockIdx.x * blockDim.x + threadIdx.x) >> 5;
    int lane = threadIdx.x & 31;
    if (warp >= N) return;
    float di = g_dinv2[warp];
    float acc = g_S[(long)warp * KCL + lane];
    int s = g_off_out[warp], e = g_off_out[warp + 1];
    for (int p = s; p < e; p++) {
        int c = g_csr_out[p];
        acc -= di * g_dinv2[c] * g_S[(long)c * KCL + lane];
    }
    g_LS[(long)warp * KCL + lane] = acc;
}

// ---------------- new_adj = S^T @ LS (32x32), partial per block + atomics -----
__global__ void adj_kernel(int N) {
    int tid = threadIdx.x;         // 1024
    int i = tid >> 5, j = tid & 31;
    float acc = 0.f;
    for (int n = blockIdx.x; n < N; n += gridDim.x)
        acc += g_S[(long)n * KCL + i] * g_LS[(long)n * KCL + j];
    atomicAdd(&g_adj[i * KCL + j], acc);
}

// ---------------- column sums of H ----------------
__global__ void sumH_kernel(int N) {
    int t = threadIdx.x;           // 256
    float acc = 0.f;
    for (int n = blockIdx.x; n < N; n += gridDim.x)
        acc += g_H[(long)n * D1 + t];
    atomicAdd(&g_sumH[t], acc);
}

// ---------------- finalize: embedding + pos_penalty ----------------
__global__ void finalize_kernel(float* __restrict__ out, int out_size) {
    int t = threadIdx.x;           // 256
    if (t < D1 && t < out_size) out[t] = g_sumH[t] * (1.0f / KCL);
    if (t < 32) {
        float rowsum = 0.f;
        #pragma unroll
        for (int c = 0; c < KCL; c++) rowsum += fabsf(g_adj[t * KCL + c]);
        float d = g_adj[t * KCL + t] / fmaxf(rowsum, 1e-12f);
        // MSE(norm_diag broadcast vs eye): column t contributes (K-1)*d^2 + (d-1)^2
        float val = (KCL - 1) * d * d + (d - 1.f) * (d - 1.f);
        #pragma unroll
        for (int o = 16; o > 0; o >>= 1) val += __shfl_xor_sync(0xffffffffu, val, o);
        if (t == 0 && D1 < out_size) out[D1] = val * (1.0f / (KCL * KCL));
    }
}

// ---------------- launch ----------------
extern "C" void kernel_launch(void* const* d_in, const int* in_sizes, int n_in,
                              void* d_out, int out_size) {
    const float* features = (const float*)d_in[0];      // [N,128] f32
    const int*   edges    = (const int*)d_in[1];        // [2,E]  int32 (JAX downcasts int64)
    const float* W1       = (const float*)d_in[2];      // [128,256]
    const float* b1       = (const float*)d_in[3];      // [256]
    const float* fc1W     = (const float*)d_in[4];      // [256,128]
    const float* fc1b     = (const float*)d_in[5];      // [128]
    const float* fc2W     = (const float*)d_in[6];      // [128,32]
    const float* fc2b     = (const float*)d_in[7];      // [32]
    float* out = (float*)d_out;

    int N = in_sizes[0] / F_IN;
    int E = in_sizes[1] / 2;
    int nChunks = (N + 255) / 256;

    float *p_H = nullptr, *p_abs = nullptr;
    cudaGetSymbolAddress((void**)&p_H,   g_H);
    cudaGetSymbolAddress((void**)&p_abs, g_abs);   // also serves as agg buffer

    // 1. CSR build
    zero_kernel<<<(N + 255) / 256, 256>>>(N);
    count_kernel<<<(E + 255) / 256, 256>>>(edges, E);
    {
        dim3 g1(nChunks, 2);
        scan_partial_kernel<<<g1, 256>>>(N);
        scan_blocks_kernel<<<2, SCAN_NB>>>(nChunks, N);
        scan_final_kernel<<<g1, 256>>>(N);   // also writes cursors + dinv
    }
    fill_kernel<<<(E + 255) / 256, 256>>>(edges, E);

    // 2. agg = A_hat @ X  (gather on 128-wide features; warp per node)
    agg_gather_kernel<<<(N * 32 + 255) / 256, 256>>>(features, p_abs, N);

    // 3. H = agg @ W1 + b1   [N,256]  (bias fused in GEMM epilogue)
    {
        dim3 grid(D1 / 64, (N + 63) / 64);
        gemm_kernel<0><<<grid, 256>>>(p_abs, W1, b1, p_H, N, D1, F_IN);
    }

    // 4. abstract = tanh(H @ fc1W + fc1b)  [N,128]  (overwrites agg — safe, agg is dead)
    {
        dim3 grid(D2 / 64, (N + 63) / 64);
        gemm_kernel<1><<<grid, 256>>>(p_H, fc1W, fc1b, p_abs, N, D2, D1);
    }

    // 5. S = softmax(abstract @ fc2W + fc2b)  [N,32]
    fc2_softmax_kernel<<<(N * 32 + 255) / 256, 256>>>(fc2W, fc2b, N);

    // 6. LS = L @ S
    ls_kernel<<<(N * 32 + 255) / 256, 256>>>(N);

    // 7. new_adj = S^T @ LS ; sumH
    adj_kernel<<<148, 1024>>>(N);
    sumH_kernel<<<256, 256>>>(N);

    // 8. outputs
    finalize_kernel<<<1, 256>>>(out, out_size);
}

// round 16
// speedup vs baseline: 1.9868x; 1.1993x over previous
#include <cuda_runtime.h>
#include <cuda_bf16.h>
#include <math.h>
#include <stdint.h>

// Problem constants (fixed by the dataset)
#define NMAX 50000
#define EMAX 800000
#define F_IN 128
#define D1   256
#define D2   128
#define KCL  32
#define SCAN_NB 256   // max chunk blocks (ceil(50000/256)=196)

// ---------------- scratch (device globals; no allocation allowed) -------------
__device__ float g_H  [NMAX * D1];     // GCN output             [N,256]
__device__ float g_abs[NMAX * D2];     // DUAL USE: agg=A_hat@X [N,128], then tanh(H@fc1_W+b)
__device__ float g_S  [NMAX * KCL];    // softmax assignments    [N,32]
__device__ float g_LS [NMAX * KCL];    // L @ S                  [N,32]

__device__ int   g_cnt_in [NMAX];
__device__ int   g_cnt_out[NMAX];
__device__ int   g_off_in [NMAX + 1];
__device__ int   g_off_out[NMAX + 1];
__device__ int   g_cur_in [NMAX];
__device__ int   g_cur_out[NMAX];
__device__ int   g_csr_in [EMAX];
__device__ int   g_csr_out[EMAX];
__device__ float g_dinv1[NMAX];
__device__ float g_dinv2[NMAX];

__device__ int   g_blksum[2][SCAN_NB];
__device__ int   g_blkoff[2][SCAN_NB];

__device__ float g_adj [KCL * KCL];
__device__ float g_sumH[D1];

// ---------------- small utility kernels ----------------
__global__ void zero_kernel(int n) {
    int i = blockIdx.x * blockDim.x + threadIdx.x;
    if (i < n) { g_cnt_in[i] = 0; g_cnt_out[i] = 0; }
    if (i < KCL * KCL) g_adj[i] = 0.f;
    if (i < D1) g_sumH[i] = 0.f;
}

__global__ void count_kernel(const int* __restrict__ edges, int E) {
    int e = blockIdx.x * blockDim.x + threadIdx.x;
    if (e >= E) return;
    int r = edges[e];
    int c = edges[E + e];
    atomicAdd(&g_cnt_in[c], 1);
    atomicAdd(&g_cnt_out[r], 1);
}

__global__ void scan_partial_kernel(int n) {
    const int* cnt = (blockIdx.y == 0) ? g_cnt_in : g_cnt_out;
    int idx = blockIdx.x * 256 + threadIdx.x;
    int v = (idx < n) ? cnt[idx] : 0;
    int lane = threadIdx.x & 31, wid = threadIdx.x >> 5;
    int x = v;
    #pragma unroll
    for (int o = 16; o > 0; o >>= 1) x += __shfl_xor_sync(0xffffffffu, x, o);
    __shared__ int ws[8];
    if (lane == 0) ws[wid] = x;
    __syncthreads();
    if (threadIdx.x == 0) {
        int t = 0;
        #pragma unroll
        for (int w = 0; w < 8; w++) t += ws[w];
        g_blksum[blockIdx.y][blockIdx.x] = t;
    }
}

__global__ void scan_blocks_kernel(int nChunks, int n) {
    int which = blockIdx.x;
    __shared__ int sh[SCAN_NB];
    int t = threadIdx.x;
    sh[t] = (t < nChunks) ? g_blksum[which][t] : 0;
    __syncthreads();
    #pragma unroll
    for (int d = 1; d < SCAN_NB; d <<= 1) {
        int v = (t >= d) ? sh[t - d] : 0;
        __syncthreads();
        sh[t] += v;
        __syncthreads();
    }
    if (t < nChunks) g_blkoff[which][t] = sh[t] - g_blksum[which][t];
    if (t == 0) {
        int total = sh[SCAN_NB - 1];
        if (which == 0) g_off_in[n] = total; else g_off_out[n] = total;
    }
}

__global__ void scan_final_kernel(int n) {
    int which = blockIdx.y;
    const int* cnt = (which == 0) ? g_cnt_in : g_cnt_out;
    int*       off = (which == 0) ? g_off_in : g_off_out;
    int*       cur = (which == 0) ? g_cur_in : g_cur_out;
    int idx = blockIdx.x * 256 + threadIdx.x;
    int v = (idx < n) ? cnt[idx] : 0;
    int lane = threadIdx.x & 31, wid = threadIdx.x >> 5;
    int x = v;
    #pragma unroll
    for (int o = 1; o < 32; o <<= 1) {
        int t = __shfl_up_sync(0xffffffffu, x, o);
        if (lane >= o) x += t;
    }
    __shared__ int ws[8];
    if (lane == 31) ws[wid] = x;
    __syncthreads();
    if (wid == 0) {
        int wv = (lane < 8) ? ws[lane] : 0;
        #pragma unroll
        for (int o = 1; o < 8; o <<= 1) {
            int t = __shfl_up_sync(0xffffffffu, wv, o);
            if (lane >= o) wv += t;
        }
        if (lane < 8) ws[lane] = wv;
    }
    __syncthreads();
    int warpExcl = (wid == 0) ? 0 : ws[wid - 1];
    int excl = g_blkoff[which][blockIdx.x] + warpExcl + (x - v);
    if (idx < n) {
        off[idx] = excl;
        cur[idx] = excl;
        if (which == 0) g_dinv1[idx] = rsqrtf((float)v + 1.0f);
        else            g_dinv2[idx] = (v > 0) ? rsqrtf((float)v) : 0.0f;
    }
}

__global__ void fill_kernel(const int* __restrict__ edges, int E) {
    int e = blockIdx.x * blockDim.x + threadIdx.x;
    if (e >= E) return;
    int r = edges[e];
    int c = edges[E + e];
    int p = atomicAdd(&g_cur_in[c], 1);
    g_csr_in[p] = r;
    int q = atomicAdd(&g_cur_out[r], 1);
    g_csr_out[q] = c;
}

// ---------------- feature aggregation (R13-proven) ----------------
__global__ void agg_gather_kernel(const float* __restrict__ feat,
                                  float* __restrict__ agg, int N) {
    int w = (blockIdx.x * blockDim.x + threadIdx.x) >> 5;
    int lane = threadIdx.x & 31;
    if (w >= N) return;
    const float4* f4 = (const float4*)feat;
    float di = g_dinv1[w];
    float4 v = f4[(long)w * 32 + lane];
    float s0 = di * di;
    float4 acc;
    acc.x = s0 * v.x; acc.y = s0 * v.y; acc.z = s0 * v.z; acc.w = s0 * v.w;
    int s = g_off_in[w], e = g_off_in[w + 1];
    for (int p = s; p < e; p++) {
        int j = g_csr_in[p];
        float sc = di * g_dinv1[j];
        float4 x = f4[(long)j * 32 + lane];
        acc.x += sc * x.x; acc.y += sc * x.y; acc.z += sc * x.z; acc.w += sc * x.w;
    }
    ((float4*)agg)[(long)w * 32 + lane] = acc;
}

// ============ tensor-core GEMM via baseline mma.sync (bf16, fp32 accum) ======
// C[M,N] = op(A[M,K] @ W[K,N] + bias).  3-term bf16 split: hh + hl + lh.
// CTA tile 128x128, BK=32; 8 warps, warp tile 64x32 (4x4 m16n8k16 atoms).
// EPI: 0 = none, 1 = tanh.
__device__ __forceinline__ void mma16816(float* c, const uint32_t* a, const uint32_t* b) {
    asm volatile(
        "mma.sync.aligned.m16n8k16.row.col.f32.bf16.bf16.f32 "
        "{%0,%1,%2,%3}, {%4,%5,%6,%7}, {%8,%9}, {%0,%1,%2,%3};"
        : "+f"(c[0]), "+f"(c[1]), "+f"(c[2]), "+f"(c[3])
        : "r"(a[0]), "r"(a[1]), "r"(a[2]), "r"(a[3]), "r"(b[0]), "r"(b[1]));
}
__device__ __forceinline__ void split_bf16(float x, __nv_bfloat16& h, __nv_bfloat16& l) {
    h = __float2bfloat16(x);
    l = __float2bfloat16(x - __bfloat162float(h));
}

template <int EPI>
__global__ __launch_bounds__(256, 1)
void mma_gemm_kernel(const float* __restrict__ A, const float* __restrict__ W,
                     const float* __restrict__ bias, float* __restrict__ C,
                     int M, int N, int K) {
    const int BK = 32, PAD = 8, LDS_K = BK + PAD;   // row stride 40 bf16 = 80B (conflict-free)
    __shared__ __nv_bfloat16 AsH[128][LDS_K], AsL[128][LDS_K];
    __shared__ __nv_bfloat16 BsH[128][LDS_K], BsL[128][LDS_K];   // B transposed: [n][k]

    int tid = threadIdx.x;
    int wid = tid >> 5, lane = tid & 31;
    int g = lane >> 2, tig = lane & 3;
    int mw = wid >> 2;          // 0..1  (64-row slice)
    int nw = wid & 3;           // 0..3  (32-col slice)
    int rowBase = blockIdx.y * 128;
    int colBase = blockIdx.x * 128;

    float acc[4][4][4] = {};    // [m-atom][n-atom][c0..c3]

    for (int k0 = 0; k0 < K; k0 += BK) {
        // ---- A tile: row = tid>>1 (0..127), kq = (tid&1)*16; fp32 -> hi/lo bf16
        {
            int ar = tid >> 1;
            int aq = (tid & 1) * 16;
            int gr = rowBase + ar;
            const float* ap = A + (long)gr * K + k0 + aq;
            #pragma unroll
            for (int i = 0; i < 16; i += 4) {
                float4 v = (gr < M) ? *(const float4*)(ap + i)
                                    : make_float4(0.f, 0.f, 0.f, 0.f);
                __nv_bfloat16 h, l;
                split_bf16(v.x, h, l); AsH[ar][aq+i+0] = h; AsL[ar][aq+i+0] = l;
                split_bf16(v.y, h, l); AsH[ar][aq+i+1] = h; AsL[ar][aq+i+1] = l;
                split_bf16(v.z, h, l); AsH[ar][aq+i+2] = h; AsL[ar][aq+i+2] = l;
                split_bf16(v.w, h, l); AsH[ar][aq+i+3] = h; AsL[ar][aq+i+3] = l;
            }
        }
        // ---- B tile transposed: W[K][N] row-major -> Bs[n][k]; coalesced on n
        {
            int bn = tid & 127;
            int bk2 = tid >> 7;             // 0 or 1
            #pragma unroll
            for (int i = 0; i < 16; i++) {
                int k = i * 2 + bk2;
                float x = W[(long)(k0 + k) * N + colBase + bn];
                __nv_bfloat16 h, l;
                split_bf16(x, h, l);
                BsH[bn][k] = h; BsL[bn][k] = l;
            }
        }
        __syncthreads();

        #pragma unroll
        for (int kk = 0; kk < BK; kk += 16) {
            uint32_t ah[4][4], al[4][4];
            #pragma unroll
            for (int ma = 0; ma < 4; ma++) {
                int r0 = mw * 64 + ma * 16 + g;
                ah[ma][0] = *(const uint32_t*)&AsH[r0    ][kk + tig*2];
                ah[ma][1] = *(const uint32_t*)&AsH[r0 + 8][kk + tig*2];
                ah[ma][2] = *(const uint32_t*)&AsH[r0    ][kk + tig*2 + 8];
                ah[ma][3] = *(const uint32_t*)&AsH[r0 + 8][kk + tig*2 + 8];
                al[ma][0] = *(const uint32_t*)&AsL[r0    ][kk + tig*2];
                al[ma][1] = *(const uint32_t*)&AsL[r0 + 8][kk + tig*2];
                al[ma][2] = *(const uint32_t*)&AsL[r0    ][kk + tig*2 + 8];
                al[ma][3] = *(const uint32_t*)&AsL[r0 + 8][kk + tig*2 + 8];
            }
            uint32_t bh[4][2], bl[4][2];
            #pragma unroll
            for (int na = 0; na < 4; na++) {
                int c0 = nw * 32 + na * 8 + g;
                bh[na][0] = *(const uint32_t*)&BsH[c0][kk + tig*2];
                bh[na][1] = *(const uint32_t*)&BsH[c0][kk + tig*2 + 8];
                bl[na][0] = *(const uint32_t*)&BsL[c0][kk + tig*2];
                bl[na][1] = *(const uint32_t*)&BsL[c0][kk + tig*2 + 8];
            }
            #pragma unroll
            for (int ma = 0; ma < 4; ma++)
                #pragma unroll
                for (int na = 0; na < 4; na++) {
                    mma16816(acc[ma][na], ah[ma], bh[na]);   // hi*hi
                    mma16816(acc[ma][na], ah[ma], bl[na]);   // hi*lo
                    mma16816(acc[ma][na], al[ma], bh[na]);   // lo*hi
                }
        }
        __syncthreads();
    }

    // ---- epilogue: bias + optional tanh, direct stores
    #pragma unroll
    for (int ma = 0; ma < 4; ma++) {
        int r0 = rowBase + mw * 64 + ma * 16 + g;
        #pragma unroll
        for (int na = 0; na < 4; na++) {
            int c0 = colBase + nw * 32 + na * 8 + tig * 2;
            float bz0 = bias[c0], bz1 = bias[c0 + 1];
            float v0 = acc[ma][na][0] + bz0;
            float v1 = acc[ma][na][1] + bz1;
            float v2 = acc[ma][na][2] + bz0;
            float v3 = acc[ma][na][3] + bz1;
            if (EPI == 1) { v0 = tanhf(v0); v1 = tanhf(v1); v2 = tanhf(v2); v3 = tanhf(v3); }
            if (r0 < M)     { float2 p = {v0, v1}; *(float2*)&C[(long)r0 * N + c0] = p; }
            if (r0 + 8 < M) { float2 p = {v2, v3}; *(float2*)&C[(long)(r0 + 8) * N + c0] = p; }
        }
    }
}

// ---------------- fc2 + softmax: one warp per node, lane = cluster k ----------
__global__ void fc2_softmax_kernel(const float* __restrict__ fc2W,
                                   const float* __restrict__ fc2b, int N) {
    int warp = (blockIdx.x * blockDim.x + threadIdx.x) >> 5;
    int lane = threadIdx.x & 31;
    if (warp >= N) return;
    const float* a = g_abs + (long)warp * D2;
    float av[4];
    #pragma unroll
    for (int q = 0; q < 4; q++) av[q] = a[lane + 32 * q];
    float acc = fc2b[lane];
    #pragma unroll
    for (int q = 0; q < 4; q++) {
        #pragma unroll
        for (int kk = 0; kk < 32; kk++) {
            float aval = __shfl_sync(0xffffffffu, av[q], kk);
            acc += aval * fc2W[(q * 32 + kk) * KCL + lane];
        }
    }
    float m = acc;
    #pragma unroll
    for (int o = 16; o > 0; o >>= 1) m = fmaxf(m, __shfl_xor_sync(0xffffffffu, m, o));
    float ex = __expf(acc - m);
    float sum = ex;
    #pragma unroll
    for (int o = 16; o > 0; o >>= 1) sum += __shfl_xor_sync(0xffffffffu, sum, o);
    g_S[(long)warp * KCL + lane] = ex / sum;
}

// ---------------- LS = S + gather over r's out-edges ----------
__global__ void ls_kernel(int N) {
    int warp = (blockIdx.x * blockDim.x + threadIdx.x) >> 5;
    int lane = threadIdx.x & 31;
    if (warp >= N) return;
    float di = g_dinv2[warp];
    float acc = g_S[(long)warp * KCL + lane];
    int s = g_off_out[warp], e = g_off_out[warp + 1];
    for (int p = s; p < e; p++) {
        int c = g_csr_out[p];
        acc -= di * g_dinv2[c] * g_S[(long)c * KCL + lane];
    }
    g_LS[(long)warp * KCL + lane] = acc;
}

// ---------------- new_adj = S^T @ LS (32x32) ----------------
__global__ void adj_kernel(int N) {
    int tid = threadIdx.x;
    int i = tid >> 5, j = tid & 31;
    float acc = 0.f;
    for (int n = blockIdx.x; n < N; n += gridDim.x)
        acc += g_S[(long)n * KCL + i] * g_LS[(long)n * KCL + j];
    atomicAdd(&g_adj[i * KCL + j], acc);
}

// ---------------- column sums of H ----------------
__global__ void sumH_kernel(int N) {
    int t = threadIdx.x;
    float acc = 0.f;
    for (int n = blockIdx.x; n < N; n += gridDim.x)
        acc += g_H[(long)n * D1 + t];
    atomicAdd(&g_sumH[t], acc);
}

// ---------------- finalize ----------------
__global__ void finalize_kernel(float* __restrict__ out, int out_size) {
    int t = threadIdx.x;
    if (t < D1 && t < out_size) out[t] = g_sumH[t] * (1.0f / KCL);
    if (t < 32) {
        float rowsum = 0.f;
        #pragma unroll
        for (int c = 0; c < KCL; c++) rowsum += fabsf(g_adj[t * KCL + c]);
        float d = g_adj[t * KCL + t] / fmaxf(rowsum, 1e-12f);
        float val = (KCL - 1) * d * d + (d - 1.f) * (d - 1.f);
        #pragma unroll
        for (int o = 16; o > 0; o >>= 1) val += __shfl_xor_sync(0xffffffffu, val, o);
        if (t == 0 && D1 < out_size) out[D1] = val * (1.0f / (KCL * KCL));
    }
}

// ---------------- launch ----------------
extern "C" void kernel_launch(void* const* d_in, const int* in_sizes, int n_in,
                              void* d_out, int out_size) {
    const float* features = (const float*)d_in[0];
    const int*   edges    = (const int*)d_in[1];
    const float* W1       = (const float*)d_in[2];      // [128,256]
    const float* b1       = (const float*)d_in[3];
    const float* fc1W     = (const float*)d_in[4];      // [256,128]
    const float* fc1b     = (const float*)d_in[5];
    const float* fc2W     = (const float*)d_in[6];
    const float* fc2b     = (const float*)d_in[7];
    float* out = (float*)d_out;

    int N = in_sizes[0] / F_IN;
    int E = in_sizes[1] / 2;
    int nChunks = (N + 255) / 256;
    int nRowTiles = (N + 127) / 128;

    float *p_H = nullptr, *p_abs = nullptr;
    cudaGetSymbolAddress((void**)&p_H,   g_H);
    cudaGetSymbolAddress((void**)&p_abs, g_abs);

    // 1. CSR build
    zero_kernel<<<(N + 255) / 256, 256>>>(N);
    count_kernel<<<(E + 255) / 256, 256>>>(edges, E);
    {
        dim3 g1(nChunks, 2);
        scan_partial_kernel<<<g1, 256>>>(N);
        scan_blocks_kernel<<<2, SCAN_NB>>>(nChunks, N);
        scan_final_kernel<<<g1, 256>>>(N);
    }
    fill_kernel<<<(E + 255) / 256, 256>>>(edges, E);

    // 2. agg = A_hat @ X  (warp per node)
    agg_gather_kernel<<<(N * 32 + 255) / 256, 256>>>(features, p_abs, N);

    // 3. H = agg @ W1 + b1   [N,256]   (HMMA bf16 3-term split)  M=N, N=256, K=128
    {
        dim3 grid(D1 / 128, nRowTiles);
        mma_gemm_kernel<0><<<grid, 256>>>(p_abs, W1, b1, p_H, N, D1, F_IN);
    }

    // 4. abstract = tanh(H @ fc1W + fc1b)  [N,128]   M=N, N=128, K=256
    {
        dim3 grid(D2 / 128, nRowTiles);
        mma_gemm_kernel<1><<<grid, 256>>>(p_H, fc1W, fc1b, p_abs, N, D2, D1);
    }

    // 5. S = softmax(abstract @ fc2W + fc2b)  [N,32]
    fc2_softmax_kernel<<<(N * 32 + 255) / 256, 256>>>(fc2W, fc2b, N);

    // 6. LS = L @ S
    ls_kernel<<<(N * 32 + 255) / 256, 256>>>(N);

    // 7. new_adj = S^T @ LS ; sumH
    adj_kernel<<<148, 1024>>>(N);
    sumH_kernel<<<256, 256>>>(N);

    // 8. outputs
    finalize_kernel<<<1, 256>>>(out, out_size);
}